// round 13
// baseline (speedup 1.0000x reference)
#include <cuda_runtime.h>
#include <cuda_bf16.h>
#include <math.h>
#include <stdint.h>

#define BB 8
#define NN 1024
#define FIN 512
#define FOUT 512
#define RR 16
#define WROWS (3*FOUT)
#define QKV_ELEMS (BB*8*NN*64)
#define NROWS (BB*8*NN)

__device__ float g_Wpf[(size_t)WROWS*FIN];
__device__ float g_qkv[3ULL*QKV_ELEMS];
__device__ __nv_bfloat16 g_vth[(size_t)QKV_ELEMS];
__device__ __nv_bfloat16 g_vtl[(size_t)QKV_ELEMS];
__device__ unsigned int g_adjbits[BB*NN*32];
__device__ unsigned int g_absmax[2];
__device__ unsigned int g_zmin_bits;
__device__ float g_rowmax[NROWS];
__device__ float g_rowsum[NROWS];

#if !defined(__CUDA_ARCH__) || defined(__CUDA_ARCH_FEAT_SM103_ALL)
#define HAS_TC 1
__device__ __forceinline__ uint32_t smem_u32(const void* p) {
    uint32_t a;
    asm("{ .reg .u64 t; cvta.to.shared.u64 t, %1; cvt.u32.u64 %0, t; }" : "=r"(a) : "l"(p));
    return a;
}
__device__ __forceinline__ uint32_t elect1() {
    uint32_t p;
    asm volatile("{ .reg .pred p; elect.sync _|p, 0xFFFFFFFF; selp.b32 %0, 1, 0, p; }" : "=r"(p));
    return p;
}
__device__ __forceinline__ uint64_t mk_desc(uint32_t addr) {
    return ((uint64_t)2 << 61) | ((uint64_t)1 << 46) | ((uint64_t)64 << 32) |
           ((uint64_t)1 << 16) | ((addr >> 4) & 0x3FFF);
}
__device__ __forceinline__ void mma_bf16_ss(uint32_t d, uint64_t ad, uint64_t bd,
                                            uint32_t idesc, uint32_t en) {
    asm volatile(
        "{\n\t.reg .pred p;\n\tsetp.ne.u32 p, %5, 0;\n\t"
        "tcgen05.mma.cta_group::1.kind::f16 [%0], %1, %2, %3, {%4, %4, %4, %4}, p;\n\t}"
        :: "r"(d), "l"(ad), "l"(bd), "r"(idesc), "r"(0u), "r"(en) : "memory");
}
__device__ __forceinline__ void mbar_wait(uint32_t mbar, uint32_t ph) {
    uint32_t done = 0;
    do {
        asm volatile(
            "{\n\t.reg .pred p;\n\t"
            "mbarrier.try_wait.parity.acquire.cta.shared::cta.b64 p, [%1], %2, 0x989680;\n\t"
            "selp.b32 %0, 1, 0, p;\n\t}" : "=r"(done) : "r"(mbar), "r"(ph) : "memory");
    } while (!done);
}
#define TALLOC(sm,n) asm volatile("tcgen05.alloc.cta_group::1.sync.aligned.shared::cta.b32 [%0], %1;" :: "r"(sm), "r"(n) : "memory")
#define TDEALLOC(t,n) asm volatile("tcgen05.dealloc.cta_group::1.sync.aligned.b32 %0, %1;" :: "r"(t), "r"(n))
#define TRELINQ() asm volatile("tcgen05.relinquish_alloc_permit.cta_group::1.sync.aligned;")
#define TCOMMIT(mb) asm volatile("tcgen05.commit.cta_group::1.mbarrier::arrive::one.shared::cluster.b64 [%0];" :: "r"(mb) : "memory")
#define MBINIT(mb,c) asm volatile("mbarrier.init.shared.b64 [%0], %1;" :: "r"(mb), "r"(c) : "memory")
#define TFENCE_A() asm volatile("tcgen05.fence::after_thread_sync;" ::: "memory")
#define TFENCE_B() asm volatile("tcgen05.fence::before_thread_sync;" ::: "memory")
#define TWAIT_LD() asm volatile("tcgen05.wait::ld.sync.aligned;" ::: "memory")
#define FENCE_ASYNC() asm volatile("fence.proxy.async.shared::cta;" ::: "memory")
#define LDTM32(r, addr) \
    asm volatile("tcgen05.ld.sync.aligned.32x32b.x32.b32 " \
        "{%0,%1,%2,%3,%4,%5,%6,%7,%8,%9,%10,%11,%12,%13,%14,%15," \
        "%16,%17,%18,%19,%20,%21,%22,%23,%24,%25,%26,%27,%28,%29,%30,%31}, [%32];" \
        : "=r"((r)[0]),"=r"((r)[1]),"=r"((r)[2]),"=r"((r)[3]),"=r"((r)[4]),"=r"((r)[5]), \
          "=r"((r)[6]),"=r"((r)[7]),"=r"((r)[8]),"=r"((r)[9]),"=r"((r)[10]),"=r"((r)[11]), \
          "=r"((r)[12]),"=r"((r)[13]),"=r"((r)[14]),"=r"((r)[15]),"=r"((r)[16]),"=r"((r)[17]), \
          "=r"((r)[18]),"=r"((r)[19]),"=r"((r)[20]),"=r"((r)[21]),"=r"((r)[22]),"=r"((r)[23]), \
          "=r"((r)[24]),"=r"((r)[25]),"=r"((r)[26]),"=r"((r)[27]),"=r"((r)[28]),"=r"((r)[29]), \
          "=r"((r)[30]),"=r"((r)[31]) : "r"(addr))
#define IDESC_N128 ((1u<<4)|(1u<<7)|(1u<<10)|(16u<<17)|(8u<<24))
#define IDESC_N64  ((1u<<4)|(1u<<7)|(1u<<10)|(8u<<17)|(8u<<24))

__device__ __forceinline__ void ld_tile(char* dst, const __nv_bfloat16* src,
                                        int rows, int stride_elems, int t, int nt) {
    int total = rows * 8;
    for (int i = t; i < total; i += nt) {
        int r = i >> 3, c = i & 7;
        int4 v = __ldg((const int4*)(src + (size_t)r*stride_elems) + c);
        int off = (r << 7) + (c << 4);
        off ^= (off >> 3) & 0x70;
        *(int4*)(dst + off) = v;
    }
}
__device__ __forceinline__ void ffma2(unsigned long long& acc,
                                      unsigned long long a2, unsigned long long b2) {
    asm("fma.rn.f32x2 %0, %1, %2, %0;" : "+l"(acc) : "l"(a2), "l"(b2));
}
__device__ __forceinline__ unsigned long long pkf2(float a, float b) {
    unsigned long long r;
    asm("mov.b64 %0, {%1, %2};" : "=l"(r) : "f"(a), "f"(b));
    return r;
}
__device__ __forceinline__ void upkf2(float& a, float& b, unsigned long long v) {
    asm("mov.b64 {%0, %1}, %2;" : "=f"(a), "=f"(b) : "l"(v));
}
#endif

__device__ __forceinline__ uint32_t pkbf2(float a, float b) {
    return (uint32_t)__bfloat16_as_ushort(__float2bfloat16(a)) |
           ((uint32_t)__bfloat16_as_ushort(__float2bfloat16(b)) << 16);
}
__device__ __forceinline__ float q1f(float v, float s) {
    return fminf(fmaxf(rintf(v / s), -127.f), 127.f);
}
#ifdef HAS_TC
// load rows x 64 fp32, quantize -> exact-int bf16, SW128 smem
__device__ __forceinline__ void ld_tile_qz(char* dst, const float* src, int rows,
                                           float s, int t, int nt) {
    int total = rows * 16;
    for (int i = t; i < total; i += nt) {
        int r = i >> 4, c = i & 15;
        float4 v = __ldg((const float4*)(src + (size_t)r*64) + c);
        uint2 p = make_uint2(pkbf2(q1f(v.x,s), q1f(v.y,s)),
                             pkbf2(q1f(v.z,s), q1f(v.w,s)));
        int off = (r << 7) + (c << 3);
        off ^= (off >> 3) & 0x70;
        *(uint2*)(dst + off) = p;
    }
}
#endif

__global__ void k_init() { g_absmax[0]=0u; g_absmax[1]=0u; g_zmin_bits=0x7f7fffffu; }

// K1: DoRA merge (y<3) fused with adjbits (y==3)
__global__ void k_merge_adj(const float* __restrict__ W0, const float* __restrict__ A0,
                            const float* __restrict__ B0, const float* __restrict__ m0,
                            const float* __restrict__ W1, const float* __restrict__ A1,
                            const float* __restrict__ B1, const float* __restrict__ m1,
                            const float* __restrict__ W2, const float* __restrict__ A2,
                            const float* __restrict__ B2, const float* __restrict__ m2,
                            const int* __restrict__ adj) {
    int t = threadIdx.x;
    if (blockIdx.y == 3) {
        int base = blockIdx.x*512 + t;
        #pragma unroll
        for (int u = 0; u < 2; u++) {
            int w = base + u*256;
            const int4* p = (const int4*)(adj + (size_t)w*32);
            unsigned int bits = 0;
            #pragma unroll
            for (int i = 0; i < 8; i++) {
                int4 v = __ldg(p + i);
                bits |= (v.x!=0 ? 1u:0u) << (i*4+0);
                bits |= (v.y!=0 ? 1u:0u) << (i*4+1);
                bits |= (v.z!=0 ? 1u:0u) << (i*4+2);
                bits |= (v.w!=0 ? 1u:0u) << (i*4+3);
            }
            g_adjbits[w] = bits;
        }
        return;
    }
    int mat = blockIdx.y;
    const float* W  = mat == 0 ? W0 : (mat == 1 ? W1 : W2);
    const float* A  = mat == 0 ? A0 : (mat == 1 ? A1 : A2);
    const float* Bm = mat == 0 ? B0 : (mat == 1 ? B1 : B2);
    const float* mg = mat == 0 ? m0 : (mat == 1 ? m1 : m2);
    int o = blockIdx.x;
    __shared__ float bs[RR]; __shared__ float wd[FIN]; __shared__ float red[8];
    if (t < RR) bs[t] = Bm[o*RR + t];
    __syncthreads();
    float ss = 0.f;
    for (int i = t; i < FIN; i += 256) {
        float v = W[o*FIN + i];
        #pragma unroll
        for (int r = 0; r < RR; r++) v += bs[r]*A[r*FIN + i];
        wd[i] = v; ss += v*v;
    }
    #pragma unroll
    for (int off = 16; off; off >>= 1) ss += __shfl_xor_sync(0xffffffffu, ss, off);
    if ((t & 31) == 0) red[t >> 5] = ss;
    __syncthreads();
    if (t == 0) {
        float tot = 0.f;
        #pragma unroll
        for (int w = 0; w < 8; w++) tot += red[w];
        red[0] = mg[o] / sqrtf(tot);
    }
    __syncthreads();
    float sc = red[0];
    size_t grow = (size_t)(mat*FOUT + o)*FIN;
    for (int i = t; i < FIN; i += 256) g_Wpf[grow + i] = wd[i]*sc;
}

// K2: SIMT fp32 projection; double-buffered + FFMA2 (bit-identical)
__global__ void __launch_bounds__(256) k_proj(const float* __restrict__ X) {
    const int BK = 16;
    __shared__ float As[2][BK][132];
    __shared__ float Bs[2][BK][132];
    int t = threadIdx.x;
    int tr = t >> 4, tc = t & 15;
    int rowBase = blockIdx.x*128, colBase = blockIdx.y*128;
    int mA0 = t >> 2, kvA = (t & 3) << 2;
    int mA1 = (t + 256) >> 2;
    float4 pa0, pa1, pb0, pb1;
    pa0 = *(const float4*)&X[(size_t)(rowBase+mA0)*FIN + kvA];
    pb0 = *(const float4*)&g_Wpf[(size_t)(colBase+mA0)*FIN + kvA];
    pa1 = *(const float4*)&X[(size_t)(rowBase+mA1)*FIN + kvA];
    pb1 = *(const float4*)&g_Wpf[(size_t)(colBase+mA1)*FIN + kvA];
#if defined(__CUDA_ARCH__) && defined(__CUDA_ARCH_FEAT_SM103_ALL)
    unsigned long long acc2[8][4];
    #pragma unroll
    for (int i = 0; i < 8; i++)
        #pragma unroll
        for (int j = 0; j < 4; j++) acc2[i][j] = 0ULL;
#else
    float acc[8][8];
    #pragma unroll
    for (int i = 0; i < 8; i++)
        #pragma unroll
        for (int j = 0; j < 8; j++) acc[i][j] = 0.f;
#endif
    for (int kc = 0; kc < FIN/BK; kc++) {
        int buf = kc & 1;
        As[buf][kvA][mA0]=pa0.x; As[buf][kvA+1][mA0]=pa0.y; As[buf][kvA+2][mA0]=pa0.z; As[buf][kvA+3][mA0]=pa0.w;
        Bs[buf][kvA][mA0]=pb0.x; Bs[buf][kvA+1][mA0]=pb0.y; Bs[buf][kvA+2][mA0]=pb0.z; Bs[buf][kvA+3][mA0]=pb0.w;
        As[buf][kvA][mA1]=pa1.x; As[buf][kvA+1][mA1]=pa1.y; As[buf][kvA+2][mA1]=pa1.z; As[buf][kvA+3][mA1]=pa1.w;
        Bs[buf][kvA][mA1]=pb1.x; Bs[buf][kvA+1][mA1]=pb1.y; Bs[buf][kvA+2][mA1]=pb1.z; Bs[buf][kvA+3][mA1]=pb1.w;
        __syncthreads();
        if (kc + 1 < FIN/BK) {
            int k0n = (kc + 1)*BK;
            pa0 = *(const float4*)&X[(size_t)(rowBase+mA0)*FIN + k0n + kvA];
            pb0 = *(const float4*)&g_Wpf[(size_t)(colBase+mA0)*FIN + k0n + kvA];
            pa1 = *(const float4*)&X[(size_t)(rowBase+mA1)*FIN + k0n + kvA];
            pb1 = *(const float4*)&g_Wpf[(size_t)(colBase+mA1)*FIN + k0n + kvA];
        }
        #pragma unroll
        for (int k = 0; k < BK; k++) {
            float4 a0 = *(const float4*)&As[buf][k][tr*8];
            float4 a1 = *(const float4*)&As[buf][k][tr*8+4];
            float ar[8] = {a0.x,a0.y,a0.z,a0.w,a1.x,a1.y,a1.z,a1.w};
#if defined(__CUDA_ARCH__) && defined(__CUDA_ARCH_FEAT_SM103_ALL)
            ulonglong2 b01 = *(const ulonglong2*)&Bs[buf][k][tc*4];
            ulonglong2 b23 = *(const ulonglong2*)&Bs[buf][k][64 + tc*4];
            #pragma unroll
            for (int i = 0; i < 8; i++) {
                unsigned long long a2 = pkf2(ar[i], ar[i]);
                ffma2(acc2[i][0], a2, b01.x);
                ffma2(acc2[i][1], a2, b01.y);
                ffma2(acc2[i][2], a2, b23.x);
                ffma2(acc2[i][3], a2, b23.y);
            }
#else
            float4 b0 = *(const float4*)&Bs[buf][k][tc*8];
            float4 b1 = *(const float4*)&Bs[buf][k][tc*8+4];
            float br[8] = {b0.x,b0.y,b0.z,b0.w,b1.x,b1.y,b1.z,b1.w};
            #pragma unroll
            for (int i = 0; i < 8; i++)
                #pragma unroll
                for (int j = 0; j < 8; j++) acc[i][j] += ar[i]*br[j];
#endif
        }
    }
    int mat = colBase >> 9;
    float amax = 0.f;
    #pragma unroll
    for (int i = 0; i < 8; i++) {
        int r = rowBase + tr*8 + i;
        int b = r >> 10, n = r & 1023;
        #pragma unroll
        for (int jv = 0; jv < 2; jv++) {
#if defined(__CUDA_ARCH__) && defined(__CUDA_ARCH_FEAT_SM103_ALL)
            int c = colBase + jv*64 + tc*4;
            float4 v;
            upkf2(v.x, v.y, acc2[i][jv*2]);
            upkf2(v.z, v.w, acc2[i][jv*2+1]);
#else
            int c = colBase + tc*8 + jv*4;
            float4 v = make_float4(acc[i][jv*4], acc[i][jv*4+1], acc[i][jv*4+2], acc[i][jv*4+3]);
#endif
            int o = c & 511, h = o >> 6, d = o & 63;
            *(float4*)&g_qkv[(size_t)mat*QKV_ELEMS + ((size_t)(((b<<3)+h)<<10) + n)*64 + d] = v;
            if (mat < 2)
                amax = fmaxf(amax, fmaxf(fmaxf(fabsf(v.x),fabsf(v.y)), fmaxf(fabsf(v.z),fabsf(v.w))));
        }
    }
    if (mat < 2) {
        #pragma unroll
        for (int off = 16; off; off >>= 1)
            amax = fmaxf(amax, __shfl_xor_sync(0xffffffffu, amax, off));
        if ((t & 31) == 0) atomicMax(&g_absmax[mat], __float_as_uint(amax));
    }
}

// K3 pass1 (launch #4 -> profiled): on-the-fly quant + tcgen05 scores
//     -> row stats + raw masked scores streamed to attn buffer
#define P1_SMEM (1024 + 2*16384)
__global__ void __launch_bounds__(128) k_pass1(float* __restrict__ attn) {
#ifdef HAS_TC
    extern __shared__ char sm[];
    uint32_t smb = smem_u32(sm);
    int t = threadIdx.x, wid = t >> 5;
    int ntile = blockIdx.x, bh = blockIdx.y, b = bh >> 3;
    if (wid == 0) { TALLOC(smb, 128); TRELINQ(); }
    __syncthreads();
    uint32_t tmem;
    asm volatile("ld.shared.b32 %0, [%1];" : "=r"(tmem) : "r"(smb));
    if (t == 0) MBINIT(smb + 8, 1);
    float sq = fmaxf(__uint_as_float(g_absmax[0]) / 127.f, 1e-8f);
    float sk = fmaxf(__uint_as_float(g_absmax[1]) / 127.f, 1e-8f);
    float sf = sq*sk;
    ld_tile_qz(sm + 1024, g_qkv + ((size_t)(bh << 10) + ntile*128)*64, 128, sq, t, 128);
    __syncthreads();
    int n = ntile*128 + t;
    const unsigned int* aw = g_adjbits + ((size_t)(b << 10) + n)*32;
    float* srow = attn + ((size_t)((bh << 10) + n))*1024;
    uint64_t qd = mk_desc(smb + 1024);
    uint64_t kd = mk_desc(smb + 1024 + 16384);
    float rmax = __int_as_float(0xff800000), rsum = 0.f;
    uint32_t ph = 0;
    for (int mt = 0; mt < 8; mt++) {
        ld_tile_qz(sm + 1024 + 16384,
                   g_qkv + QKV_ELEMS + ((size_t)(bh << 10) + mt*128)*64, 128, sk, t, 128);
        __syncthreads();
        if (wid == 0 && elect1()) {
            FENCE_ASYNC();
            #pragma unroll
            for (int ks = 0; ks < 4; ks++)
                mma_bf16_ss(tmem, qd + ks*2, kd + ks*2, IDESC_N128, ks != 0 ? 1u : 0u);
            TCOMMIT(smb + 8);
        }
        mbar_wait(smb + 8, ph); ph ^= 1;
        TFENCE_A();
        #pragma unroll
        for (int c = 0; c < 4; c++) {
            uint32_t regs[32];
            LDTM32(regs, tmem + c*32);
            TWAIT_LD();
            unsigned int bits = __ldg(&aw[mt*4 + c]);
            float sv[32], cm = -1e30f;
            #pragma unroll
            for (int j = 0; j < 32; j++) {
                float s = __uint_as_float(regs[j]) * sf;
                if (!((bits >> j) & 1u)) s = -1e9f;
                sv[j] = s; cm = fmaxf(cm, s);
            }
            float nm = fmaxf(rmax, cm);
            rsum *= expf(rmax - nm);
            #pragma unroll
            for (int j = 0; j < 32; j++) rsum += expf(sv[j] - nm);
            rmax = nm;
            #pragma unroll
            for (int j4 = 0; j4 < 8; j4++)
                *(float4*)(srow + mt*128 + c*32 + j4*4) =
                    make_float4(sv[j4*4], sv[j4*4+1], sv[j4*4+2], sv[j4*4+3]);
        }
        TFENCE_B();
        __syncthreads();
    }
    int ridx = (bh << 10) + n;
    g_rowmax[ridx] = rmax; g_rowsum[ridx] = rsum;
    float zm = rsum;
    #pragma unroll
    for (int off = 16; off; off >>= 1) zm = fminf(zm, __shfl_xor_sync(0xffffffffu, zm, off));
    if ((t & 31) == 0) atomicMin(&g_zmin_bits, __float_as_uint(zm));
    __syncthreads();
    if (wid == 0) TDEALLOC(tmem, 128);
#endif
}

// K4: V -> V^T hi/lo limbs
__global__ void k_trans_v() {
    __shared__ float ts[32][33];
    int bh = blockIdx.z, n0 = blockIdx.x*32, d0 = blockIdx.y*32;
    int tx = threadIdx.x, ty = threadIdx.y;
    const float* V = g_qkv + 2ULL*QKV_ELEMS + ((size_t)bh << 10)*64;
    for (int r = ty; r < 32; r += 8)
        ts[r][tx] = V[(size_t)(n0 + r)*64 + d0 + tx];
    __syncthreads();
    for (int r = ty; r < 32; r += 8) {
        float v = ts[tx][r];
        size_t di = ((size_t)bh*64 + d0 + r)*1024 + n0 + tx;
        __nv_bfloat16 h = __float2bfloat16(v);
        g_vth[di] = h;
        g_vtl[di] = __float2bfloat16(v - __bfloat162float(h));
    }
}

// K5: fused softmax+fake_quant+AV: reads raw scores, writes quantized attn,
//     packs P ints to smem, AV GEMM via tcgen05 (TMEM 64 cols)
#define AV_RM 1024
#define AV_Z  (AV_RM + 512)
#define AV_P  (AV_Z + 512)
#define AV_V0 (AV_P + 16384)
#define AV_V1 (AV_V0 + 8192)
#define AV_SMEM (AV_V1 + 8192)
__global__ void __launch_bounds__(128) k_av(float* __restrict__ attn,
                                            float* __restrict__ out) {
#ifdef HAS_TC
    extern __shared__ char sm[];
    uint32_t smb = smem_u32(sm);
    int t = threadIdx.x, wid = t >> 5;
    int ntile = blockIdx.x, bh = blockIdx.y, b = bh >> 3, h = bh & 7;
    if (wid == 0) { TALLOC(smb, 64); TRELINQ(); }
    __syncthreads();
    uint32_t tmem;
    asm volatile("ld.shared.b32 %0, [%1];" : "=r"(tmem) : "r"(smb));
    if (t == 0) MBINIT(smb + 8, 1);
    float* rmS = (float*)(sm + AV_RM);
    float* zS  = (float*)(sm + AV_Z);
    int rowg0 = (bh << 10) + ntile*128;
    rmS[t] = g_rowmax[rowg0 + t];
    zS[t]  = g_rowsum[rowg0 + t];
    __syncthreads();
    float s_a = fmaxf((1.0f / __uint_as_float(g_zmin_bits)) / 127.0f, 1e-8f);
    uint64_t pd = mk_desc(smb + AV_P);
    uint32_t ph = 0;
    for (int mt2 = 0; mt2 < 16; mt2++) {
        // fused: load raw scores, softmax+quant, write attn back, pack P to smem
        #pragma unroll
        for (int it = 0; it < 16; it++) {
            int i = t + it*128;
            int r = i >> 4, c = i & 15;
            float* addr = attn + ((size_t)(rowg0 + r))*1024 + mt2*64 + c*4;
            float4 s4 = *(float4*)addr;
            float rm = rmS[r], Z = zS[r];
            float p0 = fminf(rintf((expf(s4.x - rm)/Z)/s_a), 127.f);
            float p1 = fminf(rintf((expf(s4.y - rm)/Z)/s_a), 127.f);
            float p2 = fminf(rintf((expf(s4.z - rm)/Z)/s_a), 127.f);
            float p3 = fminf(rintf((expf(s4.w - rm)/Z)/s_a), 127.f);
            *(float4*)addr = make_float4(p0*s_a, p1*s_a, p2*s_a, p3*s_a);
            int off = (r << 7) + (c << 3);
            off ^= (off >> 3) & 0x70;
            *(uint2*)(sm + AV_P + off) = make_uint2(pkbf2(p0, p1), pkbf2(p2, p3));
        }
        ld_tile(sm + AV_V0, g_vth + ((size_t)bh*64)*1024 + mt2*64, 64, 1024, t, 128);
        ld_tile(sm + AV_V1, g_vtl + ((size_t)bh*64)*1024 + mt2*64, 64, 1024, t, 128);
        __syncthreads();
        if (wid == 0 && elect1()) {
            FENCE_ASYNC();
            #pragma unroll
            for (int limb = 0; limb < 2; limb++) {
                uint64_t vd = mk_desc(smb + (limb ? AV_V1 : AV_V0));
                #pragma unroll
                for (int ks = 0; ks < 4; ks++)
                    mma_bf16_ss(tmem, pd + ks*2, vd + ks*2, IDESC_N64,
                                (mt2 | limb | ks) != 0 ? 1u : 0u);
            }
            TCOMMIT(smb + 8);
        }
        mbar_wait(smb + 8, ph); ph ^= 1;
        __syncthreads();
    }
    TFENCE_A();
    {
        int n = ntile*128 + t;
        uint32_t r0[32], r1[32];
        LDTM32(r0, tmem);      TWAIT_LD();
        LDTM32(r1, tmem + 32); TWAIT_LD();
        float* orow = out + ((size_t)((b << 10) + n))*FOUT + h*64;
        #pragma unroll
        for (int j4 = 0; j4 < 8; j4++) {
            *(float4*)(orow + j4*4) = make_float4(
                __uint_as_float(r0[j4*4])*s_a,   __uint_as_float(r0[j4*4+1])*s_a,
                __uint_as_float(r0[j4*4+2])*s_a, __uint_as_float(r0[j4*4+3])*s_a);
            *(float4*)(orow + 32 + j4*4) = make_float4(
                __uint_as_float(r1[j4*4])*s_a,   __uint_as_float(r1[j4*4+1])*s_a,
                __uint_as_float(r1[j4*4+2])*s_a, __uint_as_float(r1[j4*4+3])*s_a);
        }
    }
    TFENCE_B();
    __syncthreads();
    if (wid == 0) TDEALLOC(tmem, 64);
#endif
}

// ---------------------------------------------------------------------------
extern "C" void kernel_launch(void* const* d_in, const int* in_sizes, int n_in,
                              void* d_out, int out_size) {
    const float* x = (const float*)d_in[0];
    const int* adj = (const int*)d_in[1];
    float* out = (float*)d_out;
    float* attn = out + (size_t)BB*NN*FOUT;

    cudaFuncSetAttribute(k_pass1, cudaFuncAttributeMaxDynamicSharedMemorySize, P1_SMEM);
    cudaFuncSetAttribute(k_av,    cudaFuncAttributeMaxDynamicSharedMemorySize, AV_SMEM);

    // launch #4 = k_pass1 -> profiled by ncu
    k_init<<<1, 1>>>();
    k_merge_adj<<<dim3(512, 4), 256>>>(
        (const float*)d_in[2],  (const float*)d_in[3],  (const float*)d_in[4],  (const float*)d_in[5],
        (const float*)d_in[6],  (const float*)d_in[7],  (const float*)d_in[8],  (const float*)d_in[9],
        (const float*)d_in[10], (const float*)d_in[11], (const float*)d_in[12], (const float*)d_in[13],
        adj);
    k_proj<<<dim3(64, 12), 256>>>(x);
    k_pass1<<<dim3(8, 64), 128, P1_SMEM>>>(attn);
    k_trans_v<<<dim3(32, 2, 64), dim3(32, 8)>>>();
    k_av<<<dim3(8, 64), 128, AV_SMEM>>>(attn, out);
}

// round 14
// speedup vs baseline: 1.2362x; 1.2362x over previous
#include <cuda_runtime.h>
#include <cuda_bf16.h>
#include <math.h>
#include <stdint.h>

#define BB 8
#define NN 1024
#define FIN 512
#define FOUT 512
#define RR 16
#define WROWS (3*FOUT)
#define QKV_ELEMS (BB*8*NN*64)
#define NROWS (BB*8*NN)

__device__ float g_Wpf[(size_t)WROWS*FIN];
__device__ float g_qkv[3ULL*QKV_ELEMS];
__device__ __nv_bfloat16 g_vth[(size_t)QKV_ELEMS];
__device__ __nv_bfloat16 g_vtl[(size_t)QKV_ELEMS];
__device__ __nv_bfloat16 g_pbf[(size_t)NROWS*NN];
__device__ unsigned int g_adjbits[BB*NN*32];
__device__ unsigned int g_absmax[2];
__device__ unsigned int g_zmin_bits;
__device__ float g_rowmax[NROWS];
__device__ float g_rowsum[NROWS];

#if !defined(__CUDA_ARCH__) || defined(__CUDA_ARCH_FEAT_SM103_ALL)
#define HAS_TC 1
__device__ __forceinline__ uint32_t smem_u32(const void* p) {
    uint32_t a;
    asm("{ .reg .u64 t; cvta.to.shared.u64 t, %1; cvt.u32.u64 %0, t; }" : "=r"(a) : "l"(p));
    return a;
}
__device__ __forceinline__ uint32_t elect1() {
    uint32_t p;
    asm volatile("{ .reg .pred p; elect.sync _|p, 0xFFFFFFFF; selp.b32 %0, 1, 0, p; }" : "=r"(p));
    return p;
}
__device__ __forceinline__ uint64_t mk_desc(uint32_t addr) {
    return ((uint64_t)2 << 61) | ((uint64_t)1 << 46) | ((uint64_t)64 << 32) |
           ((uint64_t)1 << 16) | ((addr >> 4) & 0x3FFF);
}
__device__ __forceinline__ void mma_bf16_ss(uint32_t d, uint64_t ad, uint64_t bd,
                                            uint32_t idesc, uint32_t en) {
    asm volatile(
        "{\n\t.reg .pred p;\n\tsetp.ne.u32 p, %5, 0;\n\t"
        "tcgen05.mma.cta_group::1.kind::f16 [%0], %1, %2, %3, {%4, %4, %4, %4}, p;\n\t}"
        :: "r"(d), "l"(ad), "l"(bd), "r"(idesc), "r"(0u), "r"(en) : "memory");
}
__device__ __forceinline__ void mbar_wait(uint32_t mbar, uint32_t ph) {
    uint32_t done = 0;
    do {
        asm volatile(
            "{\n\t.reg .pred p;\n\t"
            "mbarrier.try_wait.parity.acquire.cta.shared::cta.b64 p, [%1], %2, 0x989680;\n\t"
            "selp.b32 %0, 1, 0, p;\n\t}" : "=r"(done) : "r"(mbar), "r"(ph) : "memory");
    } while (!done);
}
#define TALLOC(sm,n) asm volatile("tcgen05.alloc.cta_group::1.sync.aligned.shared::cta.b32 [%0], %1;" :: "r"(sm), "r"(n) : "memory")
#define TDEALLOC(t,n) asm volatile("tcgen05.dealloc.cta_group::1.sync.aligned.b32 %0, %1;" :: "r"(t), "r"(n))
#define TRELINQ() asm volatile("tcgen05.relinquish_alloc_permit.cta_group::1.sync.aligned;")
#define TCOMMIT(mb) asm volatile("tcgen05.commit.cta_group::1.mbarrier::arrive::one.shared::cluster.b64 [%0];" :: "r"(mb) : "memory")
#define MBINIT(mb,c) asm volatile("mbarrier.init.shared.b64 [%0], %1;" :: "r"(mb), "r"(c) : "memory")
#define TFENCE_A() asm volatile("tcgen05.fence::after_thread_sync;" ::: "memory")
#define TFENCE_B() asm volatile("tcgen05.fence::before_thread_sync;" ::: "memory")
#define TWAIT_LD() asm volatile("tcgen05.wait::ld.sync.aligned;" ::: "memory")
#define FENCE_ASYNC() asm volatile("fence.proxy.async.shared::cta;" ::: "memory")
#define LDTM32(r, addr) \
    asm volatile("tcgen05.ld.sync.aligned.32x32b.x32.b32 " \
        "{%0,%1,%2,%3,%4,%5,%6,%7,%8,%9,%10,%11,%12,%13,%14,%15," \
        "%16,%17,%18,%19,%20,%21,%22,%23,%24,%25,%26,%27,%28,%29,%30,%31}, [%32];" \
        : "=r"((r)[0]),"=r"((r)[1]),"=r"((r)[2]),"=r"((r)[3]),"=r"((r)[4]),"=r"((r)[5]), \
          "=r"((r)[6]),"=r"((r)[7]),"=r"((r)[8]),"=r"((r)[9]),"=r"((r)[10]),"=r"((r)[11]), \
          "=r"((r)[12]),"=r"((r)[13]),"=r"((r)[14]),"=r"((r)[15]),"=r"((r)[16]),"=r"((r)[17]), \
          "=r"((r)[18]),"=r"((r)[19]),"=r"((r)[20]),"=r"((r)[21]),"=r"((r)[22]),"=r"((r)[23]), \
          "=r"((r)[24]),"=r"((r)[25]),"=r"((r)[26]),"=r"((r)[27]),"=r"((r)[28]),"=r"((r)[29]), \
          "=r"((r)[30]),"=r"((r)[31]) : "r"(addr))
#define IDESC_N128 ((1u<<4)|(1u<<7)|(1u<<10)|(16u<<17)|(8u<<24))
#define IDESC_N64  ((1u<<4)|(1u<<7)|(1u<<10)|(8u<<17)|(8u<<24))

__device__ __forceinline__ void ld_tile(char* dst, const __nv_bfloat16* src,
                                        int rows, int stride_elems, int t, int nt) {
    int total = rows * 8;
    for (int i = t; i < total; i += nt) {
        int r = i >> 3, c = i & 7;
        int4 v = __ldg((const int4*)(src + (size_t)r*stride_elems) + c);
        int off = (r << 7) + (c << 4);
        off ^= (off >> 3) & 0x70;
        *(int4*)(dst + off) = v;
    }
}
__device__ __forceinline__ void ffma2(unsigned long long& acc,
                                      unsigned long long a2, unsigned long long b2) {
    asm("fma.rn.f32x2 %0, %1, %2, %0;" : "+l"(acc) : "l"(a2), "l"(b2));
}
__device__ __forceinline__ unsigned long long pkf2(float a, float b) {
    unsigned long long r;
    asm("mov.b64 %0, {%1, %2};" : "=l"(r) : "f"(a), "f"(b));
    return r;
}
__device__ __forceinline__ void upkf2(float& a, float& b, unsigned long long v) {
    asm("mov.b64 {%0, %1}, %2;" : "=f"(a), "=f"(b) : "l"(v));
}
#endif

__device__ __forceinline__ uint32_t pkbf2(float a, float b) {
    return (uint32_t)__bfloat16_as_ushort(__float2bfloat16(a)) |
           ((uint32_t)__bfloat16_as_ushort(__float2bfloat16(b)) << 16);
}
__device__ __forceinline__ float q1f(float v, float s) {
    return fminf(fmaxf(rintf(v / s), -127.f), 127.f);
}
#ifdef HAS_TC
__device__ __forceinline__ void ld_tile_qz(char* dst, const float* src, int rows,
                                           float s, int t, int nt) {
    int total = rows * 16;
    for (int i = t; i < total; i += nt) {
        int r = i >> 4, c = i & 15;
        float4 v = __ldg((const float4*)(src + (size_t)r*64) + c);
        uint2 p = make_uint2(pkbf2(q1f(v.x,s), q1f(v.y,s)),
                             pkbf2(q1f(v.z,s), q1f(v.w,s)));
        int off = (r << 7) + (c << 3);
        off ^= (off >> 3) & 0x70;
        *(uint2*)(dst + off) = p;
    }
}
#endif

__global__ void k_init() { g_absmax[0]=0u; g_absmax[1]=0u; g_zmin_bits=0x7f7fffffu; }

// K1: DoRA merge (y<3) fused with adjbits (y==3)
__global__ void k_merge_adj(const float* __restrict__ W0, const float* __restrict__ A0,
                            const float* __restrict__ B0, const float* __restrict__ m0,
                            const float* __restrict__ W1, const float* __restrict__ A1,
                            const float* __restrict__ B1, const float* __restrict__ m1,
                            const float* __restrict__ W2, const float* __restrict__ A2,
                            const float* __restrict__ B2, const float* __restrict__ m2,
                            const int* __restrict__ adj) {
    int t = threadIdx.x;
    if (blockIdx.y == 3) {
        int base = blockIdx.x*512 + t;
        #pragma unroll
        for (int u = 0; u < 2; u++) {
            int w = base + u*256;
            const int4* p = (const int4*)(adj + (size_t)w*32);
            unsigned int bits = 0;
            #pragma unroll
            for (int i = 0; i < 8; i++) {
                int4 v = __ldg(p + i);
                bits |= (v.x!=0 ? 1u:0u) << (i*4+0);
                bits |= (v.y!=0 ? 1u:0u) << (i*4+1);
                bits |= (v.z!=0 ? 1u:0u) << (i*4+2);
                bits |= (v.w!=0 ? 1u:0u) << (i*4+3);
            }
            g_adjbits[w] = bits;
        }
        return;
    }
    int mat = blockIdx.y;
    const float* W  = mat == 0 ? W0 : (mat == 1 ? W1 : W2);
    const float* A  = mat == 0 ? A0 : (mat == 1 ? A1 : A2);
    const float* Bm = mat == 0 ? B0 : (mat == 1 ? B1 : B2);
    const float* mg = mat == 0 ? m0 : (mat == 1 ? m1 : m2);
    int o = blockIdx.x;
    __shared__ float bs[RR]; __shared__ float wd[FIN]; __shared__ float red[8];
    if (t < RR) bs[t] = Bm[o*RR + t];
    __syncthreads();
    float ss = 0.f;
    for (int i = t; i < FIN; i += 256) {
        float v = W[o*FIN + i];
        #pragma unroll
        for (int r = 0; r < RR; r++) v += bs[r]*A[r*FIN + i];
        wd[i] = v; ss += v*v;
    }
    #pragma unroll
    for (int off = 16; off; off >>= 1) ss += __shfl_xor_sync(0xffffffffu, ss, off);
    if ((t & 31) == 0) red[t >> 5] = ss;
    __syncthreads();
    if (t == 0) {
        float tot = 0.f;
        #pragma unroll
        for (int w = 0; w < 8; w++) tot += red[w];
        red[0] = mg[o] / sqrtf(tot);
    }
    __syncthreads();
    float sc = red[0];
    size_t grow = (size_t)(mat*FOUT + o)*FIN;
    for (int i = t; i < FIN; i += 256) g_Wpf[grow + i] = wd[i]*sc;
}

// K2: SIMT fp32 projection; double-buffered + FFMA2 (bit-identical)
__global__ void __launch_bounds__(256) k_proj(const float* __restrict__ X) {
    const int BK = 16;
    __shared__ float As[2][BK][132];
    __shared__ float Bs[2][BK][132];
    int t = threadIdx.x;
    int tr = t >> 4, tc = t & 15;
    int rowBase = blockIdx.x*128, colBase = blockIdx.y*128;
    int mA0 = t >> 2, kvA = (t & 3) << 2;
    int mA1 = (t + 256) >> 2;
    float4 pa0, pa1, pb0, pb1;
    pa0 = *(const float4*)&X[(size_t)(rowBase+mA0)*FIN + kvA];
    pb0 = *(const float4*)&g_Wpf[(size_t)(colBase+mA0)*FIN + kvA];
    pa1 = *(const float4*)&X[(size_t)(rowBase+mA1)*FIN + kvA];
    pb1 = *(const float4*)&g_Wpf[(size_t)(colBase+mA1)*FIN + kvA];
#if defined(__CUDA_ARCH__) && defined(__CUDA_ARCH_FEAT_SM103_ALL)
    unsigned long long acc2[8][4];
    #pragma unroll
    for (int i = 0; i < 8; i++)
        #pragma unroll
        for (int j = 0; j < 4; j++) acc2[i][j] = 0ULL;
#else
    float acc[8][8];
    #pragma unroll
    for (int i = 0; i < 8; i++)
        #pragma unroll
        for (int j = 0; j < 8; j++) acc[i][j] = 0.f;
#endif
    for (int kc = 0; kc < FIN/BK; kc++) {
        int buf = kc & 1;
        As[buf][kvA][mA0]=pa0.x; As[buf][kvA+1][mA0]=pa0.y; As[buf][kvA+2][mA0]=pa0.z; As[buf][kvA+3][mA0]=pa0.w;
        Bs[buf][kvA][mA0]=pb0.x; Bs[buf][kvA+1][mA0]=pb0.y; Bs[buf][kvA+2][mA0]=pb0.z; Bs[buf][kvA+3][mA0]=pb0.w;
        As[buf][kvA][mA1]=pa1.x; As[buf][kvA+1][mA1]=pa1.y; As[buf][kvA+2][mA1]=pa1.z; As[buf][kvA+3][mA1]=pa1.w;
        Bs[buf][kvA][mA1]=pb1.x; Bs[buf][kvA+1][mA1]=pb1.y; Bs[buf][kvA+2][mA1]=pb1.z; Bs[buf][kvA+3][mA1]=pb1.w;
        __syncthreads();
        if (kc + 1 < FIN/BK) {
            int k0n = (kc + 1)*BK;
            pa0 = *(const float4*)&X[(size_t)(rowBase+mA0)*FIN + k0n + kvA];
            pb0 = *(const float4*)&g_Wpf[(size_t)(colBase+mA0)*FIN + k0n + kvA];
            pa1 = *(const float4*)&X[(size_t)(rowBase+mA1)*FIN + k0n + kvA];
            pb1 = *(const float4*)&g_Wpf[(size_t)(colBase+mA1)*FIN + k0n + kvA];
        }
        #pragma unroll
        for (int k = 0; k < BK; k++) {
            float4 a0 = *(const float4*)&As[buf][k][tr*8];
            float4 a1 = *(const float4*)&As[buf][k][tr*8+4];
            float ar[8] = {a0.x,a0.y,a0.z,a0.w,a1.x,a1.y,a1.z,a1.w};
#if defined(__CUDA_ARCH__) && defined(__CUDA_ARCH_FEAT_SM103_ALL)
            ulonglong2 b01 = *(const ulonglong2*)&Bs[buf][k][tc*4];
            ulonglong2 b23 = *(const ulonglong2*)&Bs[buf][k][64 + tc*4];
            #pragma unroll
            for (int i = 0; i < 8; i++) {
                unsigned long long a2 = pkf2(ar[i], ar[i]);
                ffma2(acc2[i][0], a2, b01.x);
                ffma2(acc2[i][1], a2, b01.y);
                ffma2(acc2[i][2], a2, b23.x);
                ffma2(acc2[i][3], a2, b23.y);
            }
#else
            float4 b0 = *(const float4*)&Bs[buf][k][tc*8];
            float4 b1 = *(const float4*)&Bs[buf][k][tc*8+4];
            float br[8] = {b0.x,b0.y,b0.z,b0.w,b1.x,b1.y,b1.z,b1.w};
            #pragma unroll
            for (int i = 0; i < 8; i++)
                #pragma unroll
                for (int j = 0; j < 8; j++) acc[i][j] += ar[i]*br[j];
#endif
        }
    }
    int mat = colBase >> 9;
    float amax = 0.f;
    #pragma unroll
    for (int i = 0; i < 8; i++) {
        int r = rowBase + tr*8 + i;
        int b = r >> 10, n = r & 1023;
        #pragma unroll
        for (int jv = 0; jv < 2; jv++) {
#if defined(__CUDA_ARCH__) && defined(__CUDA_ARCH_FEAT_SM103_ALL)
            int c = colBase + jv*64 + tc*4;
            float4 v;
            upkf2(v.x, v.y, acc2[i][jv*2]);
            upkf2(v.z, v.w, acc2[i][jv*2+1]);
#else
            int c = colBase + tc*8 + jv*4;
            float4 v = make_float4(acc[i][jv*4], acc[i][jv*4+1], acc[i][jv*4+2], acc[i][jv*4+3]);
#endif
            int o = c & 511, h = o >> 6, d = o & 63;
            *(float4*)&g_qkv[(size_t)mat*QKV_ELEMS + ((size_t)(((b<<3)+h)<<10) + n)*64 + d] = v;
            if (mat < 2)
                amax = fmaxf(amax, fmaxf(fmaxf(fabsf(v.x),fabsf(v.y)), fmaxf(fabsf(v.z),fabsf(v.w))));
        }
    }
    if (mat < 2) {
        #pragma unroll
        for (int off = 16; off; off >>= 1)
            amax = fmaxf(amax, __shfl_xor_sync(0xffffffffu, amax, off));
        if ((t & 31) == 0) atomicMax(&g_absmax[mat], __float_as_uint(amax));
    }
}

// K3 pass1: on-the-fly quant + tcgen05 scores -> row stats + coalesced score store
#define P1_SG (1024 + 2*16384)
#define P1_SMEM (P1_SG + 128*33*4)
__global__ void __launch_bounds__(128) k_pass1(float* __restrict__ attn) {
#ifdef HAS_TC
    extern __shared__ char sm[];
    uint32_t smb = smem_u32(sm);
    int t = threadIdx.x, wid = t >> 5;
    int ntile = blockIdx.x, bh = blockIdx.y, b = bh >> 3;
    if (wid == 0) { TALLOC(smb, 128); TRELINQ(); }
    __syncthreads();
    uint32_t tmem;
    asm volatile("ld.shared.b32 %0, [%1];" : "=r"(tmem) : "r"(smb));
    if (t == 0) MBINIT(smb + 8, 1);
    float sq = fmaxf(__uint_as_float(g_absmax[0]) / 127.f, 1e-8f);
    float sk = fmaxf(__uint_as_float(g_absmax[1]) / 127.f, 1e-8f);
    float sf = sq*sk;
    ld_tile_qz(sm + 1024, g_qkv + ((size_t)(bh << 10) + ntile*128)*64, 128, sq, t, 128);
    __syncthreads();
    int n = ntile*128 + t;
    int rowg0 = (bh << 10) + ntile*128;
    const unsigned int* aw = g_adjbits + ((size_t)(b << 10) + n)*32;
    float* SG = (float*)(sm + P1_SG);
    uint64_t qd = mk_desc(smb + 1024);
    uint64_t kd = mk_desc(smb + 1024 + 16384);
    float rmax = __int_as_float(0xff800000), rsum = 0.f;
    uint32_t ph = 0;
    for (int mt = 0; mt < 8; mt++) {
        ld_tile_qz(sm + 1024 + 16384,
                   g_qkv + QKV_ELEMS + ((size_t)(bh << 10) + mt*128)*64, 128, sk, t, 128);
        __syncthreads();
        if (wid == 0 && elect1()) {
            FENCE_ASYNC();
            #pragma unroll
            for (int ks = 0; ks < 4; ks++)
                mma_bf16_ss(tmem, qd + ks*2, kd + ks*2, IDESC_N128, ks != 0 ? 1u : 0u);
            TCOMMIT(smb + 8);
        }
        mbar_wait(smb + 8, ph); ph ^= 1;
        TFENCE_A();
        #pragma unroll
        for (int c = 0; c < 4; c++) {
            uint32_t regs[32];
            LDTM32(regs, tmem + c*32);
            TWAIT_LD();
            unsigned int bits = __ldg(&aw[mt*4 + c]);
            float sv[32], cm = -1e30f;
            #pragma unroll
            for (int j = 0; j < 32; j++) {
                float s = __uint_as_float(regs[j]) * sf;
                if (!((bits >> j) & 1u)) s = -1e9f;
                sv[j] = s; cm = fmaxf(cm, s);
            }
            float nm = fmaxf(rmax, cm);
            rsum *= expf(rmax - nm);
            #pragma unroll
            for (int j = 0; j < 32; j++) rsum += expf(sv[j] - nm);
            rmax = nm;
            // coalesced store via padded smem staging (pad 33: conflict-free)
            #pragma unroll
            for (int j = 0; j < 32; j++) SG[t*33 + j] = sv[j];
            __syncthreads();
            #pragma unroll
            for (int p = 0; p < 8; p++) {
                int f4 = t + p*128;
                int r = f4 >> 3, cf = f4 & 7;
                float4 vv;
                vv.x = SG[r*33 + cf*4 + 0];
                vv.y = SG[r*33 + cf*4 + 1];
                vv.z = SG[r*33 + cf*4 + 2];
                vv.w = SG[r*33 + cf*4 + 3];
                *(float4*)&attn[((size_t)(rowg0 + r))*1024 + mt*128 + c*32 + cf*4] = vv;
            }
            __syncthreads();
        }
        TFENCE_B();
        __syncthreads();
    }
    int ridx = (bh << 10) + n;
    g_rowmax[ridx] = rmax; g_rowsum[ridx] = rsum;
    float zm = rsum;
    #pragma unroll
    for (int off = 16; off; off >>= 1) zm = fminf(zm, __shfl_xor_sync(0xffffffffu, zm, off));
    if ((t & 31) == 0) atomicMin(&g_zmin_bits, __float_as_uint(zm));
    __syncthreads();
    if (wid == 0) TDEALLOC(tmem, 128);
#endif
}

// K4: V -> V^T hi/lo limbs
__global__ void k_trans_v() {
    __shared__ float ts[32][33];
    int bh = blockIdx.z, n0 = blockIdx.x*32, d0 = blockIdx.y*32;
    int tx = threadIdx.x, ty = threadIdx.y;
    const float* V = g_qkv + 2ULL*QKV_ELEMS + ((size_t)bh << 10)*64;
    for (int r = ty; r < 32; r += 8)
        ts[r][tx] = V[(size_t)(n0 + r)*64 + d0 + tx];
    __syncthreads();
    for (int r = ty; r < 32; r += 8) {
        float v = ts[tx][r];
        size_t di = ((size_t)bh*64 + d0 + r)*1024 + n0 + tx;
        __nv_bfloat16 h = __float2bfloat16(v);
        g_vth[di] = h;
        g_vtl[di] = __float2bfloat16(v - __bfloat162float(h));
    }
}

// K5: streaming softmax + fake_quant (full occupancy, no barriers)
__global__ void __launch_bounds__(256) k_soft(float* __restrict__ attn) {
    float zmin = __uint_as_float(g_zmin_bits);
    float s_a = fmaxf((1.0f / zmin) / 127.0f, 1e-8f);
    size_t gt = (size_t)blockIdx.x*blockDim.x + threadIdx.x;
    size_t stride = (size_t)gridDim.x*blockDim.x;
    const size_t TOT4 = (size_t)NROWS*NN/4;
    for (size_t i4 = gt; i4 < TOT4; i4 += stride) {
        size_t row = i4 >> 8;
        float rm = __ldg(&g_rowmax[row]);
        float Z  = __ldg(&g_rowsum[row]);
        float4 s4 = *(float4*)(attn + i4*4);
        float p0 = fminf(rintf((expf(s4.x - rm)/Z)/s_a), 127.f);
        float p1 = fminf(rintf((expf(s4.y - rm)/Z)/s_a), 127.f);
        float p2 = fminf(rintf((expf(s4.z - rm)/Z)/s_a), 127.f);
        float p3 = fminf(rintf((expf(s4.w - rm)/Z)/s_a), 127.f);
        *(float4*)(attn + i4*4) = make_float4(p0*s_a, p1*s_a, p2*s_a, p3*s_a);
        ((uint2*)g_pbf)[i4] = make_uint2(pkbf2(p0, p1), pkbf2(p2, p3));
    }
}

// K6: AV GEMM via tcgen05; double-buffered smem with deferred MMA waits
#define AVB 32768
#define AV_SMEM (1024 + 2*AVB)
__global__ void __launch_bounds__(128) k_av(float* __restrict__ out) {
#ifdef HAS_TC
    extern __shared__ char sm[];
    uint32_t smb = smem_u32(sm);
    int t = threadIdx.x, wid = t >> 5;
    int ntile = blockIdx.x, bh = blockIdx.y, b = bh >> 3, h = bh & 7;
    if (wid == 0) { TALLOC(smb, 64); TRELINQ(); }
    __syncthreads();
    uint32_t tmem;
    asm volatile("ld.shared.b32 %0, [%1];" : "=r"(tmem) : "r"(smb));
    if (t == 0) { MBINIT(smb + 8, 1); MBINIT(smb + 16, 1); }
    __syncthreads();
    float s_a = fmaxf((1.0f / __uint_as_float(g_zmin_bits)) / 127.0f, 1e-8f);
    uint32_t ph[2] = {0, 0};
    for (int mt2 = 0; mt2 < 16; mt2++) {
        int buf = mt2 & 1;
        char* B = sm + 1024 + buf*AVB;
        if (mt2 >= 2) { mbar_wait(smb + 8 + buf*8, ph[buf]); ph[buf] ^= 1; }  // MMA(mt2-2) freed this buf
        ld_tile(B,         g_pbf + ((size_t)((bh << 10) + ntile*128))*1024 + mt2*64, 128, 1024, t, 128);
        ld_tile(B + 16384, g_vth + ((size_t)bh*64)*1024 + mt2*64, 64, 1024, t, 128);
        ld_tile(B + 24576, g_vtl + ((size_t)bh*64)*1024 + mt2*64, 64, 1024, t, 128);
        __syncthreads();
        if (wid == 0 && elect1()) {
            FENCE_ASYNC();
            uint64_t pd = mk_desc(smb + 1024 + buf*AVB);
            #pragma unroll
            for (int limb = 0; limb < 2; limb++) {
                uint64_t vd = mk_desc(smb + 1024 + buf*AVB + 16384 + limb*8192);
                #pragma unroll
                for (int ks = 0; ks < 4; ks++)
                    mma_bf16_ss(tmem, pd + ks*2, vd + ks*2, IDESC_N64,
                                (mt2 | limb | ks) != 0 ? 1u : 0u);
            }
            TCOMMIT(smb + 8 + buf*8);
        }
    }
    mbar_wait(smb + 8,  ph[0]);   // MMA(14)
    mbar_wait(smb + 16, ph[1]);   // MMA(15)
    TFENCE_A();
    {
        int n = ntile*128 + t;
        uint32_t r0[32], r1[32];
        LDTM32(r0, tmem);      TWAIT_LD();
        LDTM32(r1, tmem + 32); TWAIT_LD();
        float* orow = out + ((size_t)((b << 10) + n))*FOUT + h*64;
        #pragma unroll
        for (int j4 = 0; j4 < 8; j4++) {
            *(float4*)(orow + j4*4) = make_float4(
                __uint_as_float(r0[j4*4])*s_a,   __uint_as_float(r0[j4*4+1])*s_a,
                __uint_as_float(r0[j4*4+2])*s_a, __uint_as_float(r0[j4*4+3])*s_a);
            *(float4*)(orow + 32 + j4*4) = make_float4(
                __uint_as_float(r1[j4*4])*s_a,   __uint_as_float(r1[j4*4+1])*s_a,
                __uint_as_float(r1[j4*4+2])*s_a, __uint_as_float(r1[j4*4+3])*s_a);
        }
    }
    TFENCE_B();
    __syncthreads();
    if (wid == 0) TDEALLOC(tmem, 64);
#endif
}

// ---------------------------------------------------------------------------
extern "C" void kernel_launch(void* const* d_in, const int* in_sizes, int n_in,
                              void* d_out, int out_size) {
    const float* x = (const float*)d_in[0];
    const int* adj = (const int*)d_in[1];
    float* out = (float*)d_out;
    float* attn = out + (size_t)BB*NN*FOUT;

    cudaFuncSetAttribute(k_pass1, cudaFuncAttributeMaxDynamicSharedMemorySize, P1_SMEM);
    cudaFuncSetAttribute(k_av,    cudaFuncAttributeMaxDynamicSharedMemorySize, AV_SMEM);

    // launch #4 = k_pass1 -> profiled by ncu
    k_init<<<1, 1>>>();
    k_merge_adj<<<dim3(512, 4), 256>>>(
        (const float*)d_in[2],  (const float*)d_in[3],  (const float*)d_in[4],  (const float*)d_in[5],
        (const float*)d_in[6],  (const float*)d_in[7],  (const float*)d_in[8],  (const float*)d_in[9],
        (const float*)d_in[10], (const float*)d_in[11], (const float*)d_in[12], (const float*)d_in[13],
        adj);
    k_proj<<<dim3(64, 12), 256>>>(x);
    k_pass1<<<dim3(8, 64), 128, P1_SMEM>>>(attn);
    k_trans_v<<<dim3(32, 2, 64), dim3(32, 8)>>>();
    k_soft<<<4096, 256>>>(attn);
    k_av<<<dim3(8, 64), 128, AV_SMEM>>>(out);
}

// round 15
// speedup vs baseline: 1.3815x; 1.1176x over previous
#include <cuda_runtime.h>
#include <cuda_bf16.h>
#include <math.h>
#include <stdint.h>

#define BB 8
#define NN 1024
#define FIN 512
#define FOUT 512
#define RR 16
#define WROWS (3*FOUT)
#define QKV_ELEMS (BB*8*NN*64)
#define NROWS (BB*8*NN)

__device__ float g_Wpf[(size_t)WROWS*FIN];
__device__ float g_qkv[3ULL*QKV_ELEMS];
__device__ __nv_bfloat16 g_vth[(size_t)QKV_ELEMS];
__device__ __nv_bfloat16 g_vtl[(size_t)QKV_ELEMS];
__device__ __nv_bfloat16 g_pbf[(size_t)NROWS*NN];
__device__ unsigned int g_adjbits[BB*NN*32];
__device__ unsigned int g_absmax[2];
__device__ unsigned int g_zmin_bits;
__device__ float g_rowmax[NROWS];
__device__ float g_rowsum[NROWS];

#if !defined(__CUDA_ARCH__) || defined(__CUDA_ARCH_FEAT_SM103_ALL)
#define HAS_TC 1
__device__ __forceinline__ uint32_t smem_u32(const void* p) {
    uint32_t a;
    asm("{ .reg .u64 t; cvta.to.shared.u64 t, %1; cvt.u32.u64 %0, t; }" : "=r"(a) : "l"(p));
    return a;
}
__device__ __forceinline__ uint32_t elect1() {
    uint32_t p;
    asm volatile("{ .reg .pred p; elect.sync _|p, 0xFFFFFFFF; selp.b32 %0, 1, 0, p; }" : "=r"(p));
    return p;
}
__device__ __forceinline__ uint64_t mk_desc(uint32_t addr) {
    return ((uint64_t)2 << 61) | ((uint64_t)1 << 46) | ((uint64_t)64 << 32) |
           ((uint64_t)1 << 16) | ((addr >> 4) & 0x3FFF);
}
__device__ __forceinline__ void mma_bf16_ss(uint32_t d, uint64_t ad, uint64_t bd,
                                            uint32_t idesc, uint32_t en) {
    asm volatile(
        "{\n\t.reg .pred p;\n\tsetp.ne.u32 p, %5, 0;\n\t"
        "tcgen05.mma.cta_group::1.kind::f16 [%0], %1, %2, %3, {%4, %4, %4, %4}, p;\n\t}"
        :: "r"(d), "l"(ad), "l"(bd), "r"(idesc), "r"(0u), "r"(en) : "memory");
}
__device__ __forceinline__ void mbar_wait(uint32_t mbar, uint32_t ph) {
    uint32_t done = 0;
    do {
        asm volatile(
            "{\n\t.reg .pred p;\n\t"
            "mbarrier.try_wait.parity.acquire.cta.shared::cta.b64 p, [%1], %2, 0x989680;\n\t"
            "selp.b32 %0, 1, 0, p;\n\t}" : "=r"(done) : "r"(mbar), "r"(ph) : "memory");
    } while (!done);
}
#define TALLOC(sm,n) asm volatile("tcgen05.alloc.cta_group::1.sync.aligned.shared::cta.b32 [%0], %1;" :: "r"(sm), "r"(n) : "memory")
#define TDEALLOC(t,n) asm volatile("tcgen05.dealloc.cta_group::1.sync.aligned.b32 %0, %1;" :: "r"(t), "r"(n))
#define TRELINQ() asm volatile("tcgen05.relinquish_alloc_permit.cta_group::1.sync.aligned;")
#define TCOMMIT(mb) asm volatile("tcgen05.commit.cta_group::1.mbarrier::arrive::one.shared::cluster.b64 [%0];" :: "r"(mb) : "memory")
#define MBINIT(mb,c) asm volatile("mbarrier.init.shared.b64 [%0], %1;" :: "r"(mb), "r"(c) : "memory")
#define TFENCE_A() asm volatile("tcgen05.fence::after_thread_sync;" ::: "memory")
#define TFENCE_B() asm volatile("tcgen05.fence::before_thread_sync;" ::: "memory")
#define TWAIT_LD() asm volatile("tcgen05.wait::ld.sync.aligned;" ::: "memory")
#define FENCE_ASYNC() asm volatile("fence.proxy.async.shared::cta;" ::: "memory")
#define LDTM32(r, addr) \
    asm volatile("tcgen05.ld.sync.aligned.32x32b.x32.b32 " \
        "{%0,%1,%2,%3,%4,%5,%6,%7,%8,%9,%10,%11,%12,%13,%14,%15," \
        "%16,%17,%18,%19,%20,%21,%22,%23,%24,%25,%26,%27,%28,%29,%30,%31}, [%32];" \
        : "=r"((r)[0]),"=r"((r)[1]),"=r"((r)[2]),"=r"((r)[3]),"=r"((r)[4]),"=r"((r)[5]), \
          "=r"((r)[6]),"=r"((r)[7]),"=r"((r)[8]),"=r"((r)[9]),"=r"((r)[10]),"=r"((r)[11]), \
          "=r"((r)[12]),"=r"((r)[13]),"=r"((r)[14]),"=r"((r)[15]),"=r"((r)[16]),"=r"((r)[17]), \
          "=r"((r)[18]),"=r"((r)[19]),"=r"((r)[20]),"=r"((r)[21]),"=r"((r)[22]),"=r"((r)[23]), \
          "=r"((r)[24]),"=r"((r)[25]),"=r"((r)[26]),"=r"((r)[27]),"=r"((r)[28]),"=r"((r)[29]), \
          "=r"((r)[30]),"=r"((r)[31]) : "r"(addr))
#define IDESC_N128 ((1u<<4)|(1u<<7)|(1u<<10)|(16u<<17)|(8u<<24))
#define IDESC_N64  ((1u<<4)|(1u<<7)|(1u<<10)|(8u<<17)|(8u<<24))

__device__ __forceinline__ void ld_tile(char* dst, const __nv_bfloat16* src,
                                        int rows, int stride_elems, int t, int nt) {
    int total = rows * 8;
    for (int i = t; i < total; i += nt) {
        int r = i >> 3, c = i & 7;
        int4 v = __ldg((const int4*)(src + (size_t)r*stride_elems) + c);
        int off = (r << 7) + (c << 4);
        off ^= (off >> 3) & 0x70;
        *(int4*)(dst + off) = v;
    }
}
__device__ __forceinline__ void ffma2(unsigned long long& acc,
                                      unsigned long long a2, unsigned long long b2) {
    asm("fma.rn.f32x2 %0, %1, %2, %0;" : "+l"(acc) : "l"(a2), "l"(b2));
}
__device__ __forceinline__ unsigned long long pkf2(float a, float b) {
    unsigned long long r;
    asm("mov.b64 %0, {%1, %2};" : "=l"(r) : "f"(a), "f"(b));
    return r;
}
__device__ __forceinline__ void upkf2(float& a, float& b, unsigned long long v) {
    asm("mov.b64 {%0, %1}, %2;" : "=f"(a), "=f"(b) : "l"(v));
}
#endif

__device__ __forceinline__ uint32_t pkbf2(float a, float b) {
    return (uint32_t)__bfloat16_as_ushort(__float2bfloat16(a)) |
           ((uint32_t)__bfloat16_as_ushort(__float2bfloat16(b)) << 16);
}
__device__ __forceinline__ float q1f(float v, float s) {
    return fminf(fmaxf(rintf(v / s), -127.f), 127.f);
}
#ifdef HAS_TC
__device__ __forceinline__ void ld_tile_qz(char* dst, const float* src, int rows,
                                           float s, int t, int nt) {
    int total = rows * 16;
    for (int i = t; i < total; i += nt) {
        int r = i >> 4, c = i & 15;
        float4 v = __ldg((const float4*)(src + (size_t)r*64) + c);
        uint2 p = make_uint2(pkbf2(q1f(v.x,s), q1f(v.y,s)),
                             pkbf2(q1f(v.z,s), q1f(v.w,s)));
        int off = (r << 7) + (c << 3);
        off ^= (off >> 3) & 0x70;
        *(uint2*)(dst + off) = p;
    }
}
#endif

__global__ void k_init() { g_absmax[0]=0u; g_absmax[1]=0u; g_zmin_bits=0x7f7fffffu; }

// K1: DoRA merge (y<3) fused with adjbits (y==3)
__global__ void k_merge_adj(const float* __restrict__ W0, const float* __restrict__ A0,
                            const float* __restrict__ B0, const float* __restrict__ m0,
                            const float* __restrict__ W1, const float* __restrict__ A1,
                            const float* __restrict__ B1, const float* __restrict__ m1,
                            const float* __restrict__ W2, const float* __restrict__ A2,
                            const float* __restrict__ B2, const float* __restrict__ m2,
                            const int* __restrict__ adj) {
    int t = threadIdx.x;
    if (blockIdx.y == 3) {
        int base = blockIdx.x*512 + t;
        #pragma unroll
        for (int u = 0; u < 2; u++) {
            int w = base + u*256;
            const int4* p = (const int4*)(adj + (size_t)w*32);
            unsigned int bits = 0;
            #pragma unroll
            for (int i = 0; i < 8; i++) {
                int4 v = __ldg(p + i);
                bits |= (v.x!=0 ? 1u:0u) << (i*4+0);
                bits |= (v.y!=0 ? 1u:0u) << (i*4+1);
                bits |= (v.z!=0 ? 1u:0u) << (i*4+2);
                bits |= (v.w!=0 ? 1u:0u) << (i*4+3);
            }
            g_adjbits[w] = bits;
        }
        return;
    }
    int mat = blockIdx.y;
    const float* W  = mat == 0 ? W0 : (mat == 1 ? W1 : W2);
    const float* A  = mat == 0 ? A0 : (mat == 1 ? A1 : A2);
    const float* Bm = mat == 0 ? B0 : (mat == 1 ? B1 : B2);
    const float* mg = mat == 0 ? m0 : (mat == 1 ? m1 : m2);
    int o = blockIdx.x;
    __shared__ float bs[RR]; __shared__ float wd[FIN]; __shared__ float red[8];
    if (t < RR) bs[t] = Bm[o*RR + t];
    __syncthreads();
    float ss = 0.f;
    for (int i = t; i < FIN; i += 256) {
        float v = W[o*FIN + i];
        #pragma unroll
        for (int r = 0; r < RR; r++) v += bs[r]*A[r*FIN + i];
        wd[i] = v; ss += v*v;
    }
    #pragma unroll
    for (int off = 16; off; off >>= 1) ss += __shfl_xor_sync(0xffffffffu, ss, off);
    if ((t & 31) == 0) red[t >> 5] = ss;
    __syncthreads();
    if (t == 0) {
        float tot = 0.f;
        #pragma unroll
        for (int w = 0; w < 8; w++) tot += red[w];
        red[0] = mg[o] / sqrtf(tot);
    }
    __syncthreads();
    float sc = red[0];
    size_t grow = (size_t)(mat*FOUT + o)*FIN;
    for (int i = t; i < FIN; i += 256) g_Wpf[grow + i] = wd[i]*sc;
}

// K2: SIMT fp32 projection; double-buffered + FFMA2 (bit-identical)
__global__ void __launch_bounds__(256) k_proj(const float* __restrict__ X) {
    const int BK = 16;
    __shared__ float As[2][BK][132];
    __shared__ float Bs[2][BK][132];
    int t = threadIdx.x;
    int tr = t >> 4, tc = t & 15;
    int rowBase = blockIdx.x*128, colBase = blockIdx.y*128;
    int mA0 = t >> 2, kvA = (t & 3) << 2;
    int mA1 = (t + 256) >> 2;
    float4 pa0, pa1, pb0, pb1;
    pa0 = *(const float4*)&X[(size_t)(rowBase+mA0)*FIN + kvA];
    pb0 = *(const float4*)&g_Wpf[(size_t)(colBase+mA0)*FIN + kvA];
    pa1 = *(const float4*)&X[(size_t)(rowBase+mA1)*FIN + kvA];
    pb1 = *(const float4*)&g_Wpf[(size_t)(colBase+mA1)*FIN + kvA];
#if defined(__CUDA_ARCH__) && defined(__CUDA_ARCH_FEAT_SM103_ALL)
    unsigned long long acc2[8][4];
    #pragma unroll
    for (int i = 0; i < 8; i++)
        #pragma unroll
        for (int j = 0; j < 4; j++) acc2[i][j] = 0ULL;
#else
    float acc[8][8];
    #pragma unroll
    for (int i = 0; i < 8; i++)
        #pragma unroll
        for (int j = 0; j < 8; j++) acc[i][j] = 0.f;
#endif
    for (int kc = 0; kc < FIN/BK; kc++) {
        int buf = kc & 1;
        As[buf][kvA][mA0]=pa0.x; As[buf][kvA+1][mA0]=pa0.y; As[buf][kvA+2][mA0]=pa0.z; As[buf][kvA+3][mA0]=pa0.w;
        Bs[buf][kvA][mA0]=pb0.x; Bs[buf][kvA+1][mA0]=pb0.y; Bs[buf][kvA+2][mA0]=pb0.z; Bs[buf][kvA+3][mA0]=pb0.w;
        As[buf][kvA][mA1]=pa1.x; As[buf][kvA+1][mA1]=pa1.y; As[buf][kvA+2][mA1]=pa1.z; As[buf][kvA+3][mA1]=pa1.w;
        Bs[buf][kvA][mA1]=pb1.x; Bs[buf][kvA+1][mA1]=pb1.y; Bs[buf][kvA+2][mA1]=pb1.z; Bs[buf][kvA+3][mA1]=pb1.w;
        __syncthreads();
        if (kc + 1 < FIN/BK) {
            int k0n = (kc + 1)*BK;
            pa0 = *(const float4*)&X[(size_t)(rowBase+mA0)*FIN + k0n + kvA];
            pb0 = *(const float4*)&g_Wpf[(size_t)(colBase+mA0)*FIN + k0n + kvA];
            pa1 = *(const float4*)&X[(size_t)(rowBase+mA1)*FIN + k0n + kvA];
            pb1 = *(const float4*)&g_Wpf[(size_t)(colBase+mA1)*FIN + k0n + kvA];
        }
        #pragma unroll
        for (int k = 0; k < BK; k++) {
            float4 a0 = *(const float4*)&As[buf][k][tr*8];
            float4 a1 = *(const float4*)&As[buf][k][tr*8+4];
            float ar[8] = {a0.x,a0.y,a0.z,a0.w,a1.x,a1.y,a1.z,a1.w};
#if defined(__CUDA_ARCH__) && defined(__CUDA_ARCH_FEAT_SM103_ALL)
            ulonglong2 b01 = *(const ulonglong2*)&Bs[buf][k][tc*4];
            ulonglong2 b23 = *(const ulonglong2*)&Bs[buf][k][64 + tc*4];
            #pragma unroll
            for (int i = 0; i < 8; i++) {
                unsigned long long a2 = pkf2(ar[i], ar[i]);
                ffma2(acc2[i][0], a2, b01.x);
                ffma2(acc2[i][1], a2, b01.y);
                ffma2(acc2[i][2], a2, b23.x);
                ffma2(acc2[i][3], a2, b23.y);
            }
#else
            float4 b0 = *(const float4*)&Bs[buf][k][tc*8];
            float4 b1 = *(const float4*)&Bs[buf][k][tc*8+4];
            float br[8] = {b0.x,b0.y,b0.z,b0.w,b1.x,b1.y,b1.z,b1.w};
            #pragma unroll
            for (int i = 0; i < 8; i++)
                #pragma unroll
                for (int j = 0; j < 8; j++) acc[i][j] += ar[i]*br[j];
#endif
        }
    }
    int mat = colBase >> 9;
    float amax = 0.f;
    #pragma unroll
    for (int i = 0; i < 8; i++) {
        int r = rowBase + tr*8 + i;
        int b = r >> 10, n = r & 1023;
        #pragma unroll
        for (int jv = 0; jv < 2; jv++) {
#if defined(__CUDA_ARCH__) && defined(__CUDA_ARCH_FEAT_SM103_ALL)
            int c = colBase + jv*64 + tc*4;
            float4 v;
            upkf2(v.x, v.y, acc2[i][jv*2]);
            upkf2(v.z, v.w, acc2[i][jv*2+1]);
#else
            int c = colBase + tc*8 + jv*4;
            float4 v = make_float4(acc[i][jv*4], acc[i][jv*4+1], acc[i][jv*4+2], acc[i][jv*4+3]);
#endif
            int o = c & 511, h = o >> 6, d = o & 63;
            *(float4*)&g_qkv[(size_t)mat*QKV_ELEMS + ((size_t)(((b<<3)+h)<<10) + n)*64 + d] = v;
            if (mat < 2)
                amax = fmaxf(amax, fmaxf(fmaxf(fabsf(v.x),fabsf(v.y)), fmaxf(fabsf(v.z),fabsf(v.w))));
        }
    }
    if (mat < 2) {
        #pragma unroll
        for (int off = 16; off; off >>= 1)
            amax = fmaxf(amax, __shfl_xor_sync(0xffffffffu, amax, off));
        if ((t & 31) == 0) atomicMax(&g_absmax[mat], __float_as_uint(amax));
    }
}

// K3 pass1: on-the-fly quant + tcgen05 scores -> row stats + coalesced score store
#define P1_SG (1024 + 2*16384)
#define P1_SMEM (P1_SG + 128*33*4)
__global__ void __launch_bounds__(128) k_pass1(float* __restrict__ attn) {
#ifdef HAS_TC
    extern __shared__ char sm[];
    uint32_t smb = smem_u32(sm);
    int t = threadIdx.x, wid = t >> 5;
    int ntile = blockIdx.x, bh = blockIdx.y, b = bh >> 3;
    if (wid == 0) { TALLOC(smb, 128); TRELINQ(); }
    __syncthreads();
    uint32_t tmem;
    asm volatile("ld.shared.b32 %0, [%1];" : "=r"(tmem) : "r"(smb));
    if (t == 0) MBINIT(smb + 8, 1);
    float sq = fmaxf(__uint_as_float(g_absmax[0]) / 127.f, 1e-8f);
    float sk = fmaxf(__uint_as_float(g_absmax[1]) / 127.f, 1e-8f);
    float sf = sq*sk;
    ld_tile_qz(sm + 1024, g_qkv + ((size_t)(bh << 10) + ntile*128)*64, 128, sq, t, 128);
    __syncthreads();
    int n = ntile*128 + t;
    int rowg0 = (bh << 10) + ntile*128;
    const unsigned int* aw = g_adjbits + ((size_t)(b << 10) + n)*32;
    float* SG = (float*)(sm + P1_SG);
    uint64_t qd = mk_desc(smb + 1024);
    uint64_t kd = mk_desc(smb + 1024 + 16384);
    float rmax = __int_as_float(0xff800000), rsum = 0.f;
    uint32_t ph = 0;
    for (int mt = 0; mt < 8; mt++) {
        ld_tile_qz(sm + 1024 + 16384,
                   g_qkv + QKV_ELEMS + ((size_t)(bh << 10) + mt*128)*64, 128, sk, t, 128);
        __syncthreads();
        if (wid == 0 && elect1()) {
            FENCE_ASYNC();
            #pragma unroll
            for (int ks = 0; ks < 4; ks++)
                mma_bf16_ss(tmem, qd + ks*2, kd + ks*2, IDESC_N128, ks != 0 ? 1u : 0u);
            TCOMMIT(smb + 8);
        }
        mbar_wait(smb + 8, ph); ph ^= 1;
        TFENCE_A();
        #pragma unroll
        for (int c = 0; c < 4; c++) {
            uint32_t regs[32];
            LDTM32(regs, tmem + c*32);
            TWAIT_LD();
            unsigned int bits = __ldg(&aw[mt*4 + c]);
            float sv[32], cm = -1e30f;
            #pragma unroll
            for (int j = 0; j < 32; j++) {
                float s = __uint_as_float(regs[j]) * sf;
                if (!((bits >> j) & 1u)) s = -1e9f;
                sv[j] = s; cm = fmaxf(cm, s);
            }
            float nm = fmaxf(rmax, cm);
            rsum *= expf(rmax - nm);
            #pragma unroll
            for (int j = 0; j < 32; j++) rsum += expf(sv[j] - nm);
            rmax = nm;
            #pragma unroll
            for (int j = 0; j < 32; j++) SG[t*33 + j] = sv[j];
            __syncthreads();
            #pragma unroll
            for (int p = 0; p < 8; p++) {
                int f4 = t + p*128;
                int r = f4 >> 3, cf = f4 & 7;
                float4 vv;
                vv.x = SG[r*33 + cf*4 + 0];
                vv.y = SG[r*33 + cf*4 + 1];
                vv.z = SG[r*33 + cf*4 + 2];
                vv.w = SG[r*33 + cf*4 + 3];
                *(float4*)&attn[((size_t)(rowg0 + r))*1024 + mt*128 + c*32 + cf*4] = vv;
            }
            __syncthreads();
        }
        TFENCE_B();
        __syncthreads();
    }
    int ridx = (bh << 10) + n;
    g_rowmax[ridx] = rmax; g_rowsum[ridx] = rsum;
    float zm = rsum;
    #pragma unroll
    for (int off = 16; off; off >>= 1) zm = fminf(zm, __shfl_xor_sync(0xffffffffu, zm, off));
    if ((t & 31) == 0) atomicMin(&g_zmin_bits, __float_as_uint(zm));
    __syncthreads();
    if (wid == 0) TDEALLOC(tmem, 128);
#endif
}

// K4: V -> V^T hi/lo limbs
__global__ void k_trans_v() {
    __shared__ float ts[32][33];
    int bh = blockIdx.z, n0 = blockIdx.x*32, d0 = blockIdx.y*32;
    int tx = threadIdx.x, ty = threadIdx.y;
    const float* V = g_qkv + 2ULL*QKV_ELEMS + ((size_t)bh << 10)*64;
    for (int r = ty; r < 32; r += 8)
        ts[r][tx] = V[(size_t)(n0 + r)*64 + d0 + tx];
    __syncthreads();
    for (int r = ty; r < 32; r += 8) {
        float v = ts[tx][r];
        size_t di = ((size_t)bh*64 + d0 + r)*1024 + n0 + tx;
        __nv_bfloat16 h = __float2bfloat16(v);
        g_vth[di] = h;
        g_vtl[di] = __float2bfloat16(v - __bfloat162float(h));
    }
}

// K5: streaming softmax + fake_quant (full occupancy, no barriers)
__global__ void __launch_bounds__(256) k_soft(float* __restrict__ attn) {
    float zmin = __uint_as_float(g_zmin_bits);
    float s_a = fmaxf((1.0f / zmin) / 127.0f, 1e-8f);
    size_t gt = (size_t)blockIdx.x*blockDim.x + threadIdx.x;
    size_t stride = (size_t)gridDim.x*blockDim.x;
    const size_t TOT4 = (size_t)NROWS*NN/4;
    for (size_t i4 = gt; i4 < TOT4; i4 += stride) {
        size_t row = i4 >> 8;
        float rm = __ldg(&g_rowmax[row]);
        float Z  = __ldg(&g_rowsum[row]);
        float4 s4 = *(float4*)(attn + i4*4);
        float p0 = fminf(rintf((expf(s4.x - rm)/Z)/s_a), 127.f);
        float p1 = fminf(rintf((expf(s4.y - rm)/Z)/s_a), 127.f);
        float p2 = fminf(rintf((expf(s4.z - rm)/Z)/s_a), 127.f);
        float p3 = fminf(rintf((expf(s4.w - rm)/Z)/s_a), 127.f);
        *(float4*)(attn + i4*4) = make_float4(p0*s_a, p1*s_a, p2*s_a, p3*s_a);
        ((uint2*)g_pbf)[i4] = make_uint2(pkbf2(p0, p1), pkbf2(p2, p3));
    }
}

// K6: AV GEMM via tcgen05 (R12 config: single buffer, 6 CTAs/SM)
#define AV_P 1024
#define AV_V0 (1024 + 16384)
#define AV_V1 (AV_V0 + 8192)
#define AV_SMEM (AV_V1 + 8192)
__global__ void __launch_bounds__(128) k_av(float* __restrict__ out) {
#ifdef HAS_TC
    extern __shared__ char sm[];
    uint32_t smb = smem_u32(sm);
    int t = threadIdx.x, wid = t >> 5;
    int ntile = blockIdx.x, bh = blockIdx.y, b = bh >> 3, h = bh & 7;
    if (wid == 0) { TALLOC(smb, 64); TRELINQ(); }
    __syncthreads();
    uint32_t tmem;
    asm volatile("ld.shared.b32 %0, [%1];" : "=r"(tmem) : "r"(smb));
    if (t == 0) MBINIT(smb + 8, 1);
    __syncthreads();
    float s_a = fmaxf((1.0f / __uint_as_float(g_zmin_bits)) / 127.0f, 1e-8f);
    uint64_t pd = mk_desc(smb + AV_P);
    uint32_t ph = 0;
    for (int mt2 = 0; mt2 < 16; mt2++) {
        ld_tile(sm + AV_P,
                g_pbf + ((size_t)((bh << 10) + ntile*128))*1024 + mt2*64, 128, 1024, t, 128);
        ld_tile(sm + AV_V0, g_vth + ((size_t)bh*64)*1024 + mt2*64, 64, 1024, t, 128);
        ld_tile(sm + AV_V1, g_vtl + ((size_t)bh*64)*1024 + mt2*64, 64, 1024, t, 128);
        __syncthreads();
        if (wid == 0 && elect1()) {
            FENCE_ASYNC();
            #pragma unroll
            for (int limb = 0; limb < 2; limb++) {
                uint64_t vd = mk_desc(smb + (limb ? AV_V1 : AV_V0));
                #pragma unroll
                for (int ks = 0; ks < 4; ks++)
                    mma_bf16_ss(tmem, pd + ks*2, vd + ks*2, IDESC_N64,
                                (mt2 | limb | ks) != 0 ? 1u : 0u);
            }
            TCOMMIT(smb + 8);
        }
        mbar_wait(smb + 8, ph); ph ^= 1;
        __syncthreads();
    }
    TFENCE_A();
    {
        int n = ntile*128 + t;
        uint32_t r0[32], r1[32];
        LDTM32(r0, tmem);      TWAIT_LD();
        LDTM32(r1, tmem + 32); TWAIT_LD();
        float* orow = out + ((size_t)((b << 10) + n))*FOUT + h*64;
        #pragma unroll
        for (int j4 = 0; j4 < 8; j4++) {
            *(float4*)(orow + j4*4) = make_float4(
                __uint_as_float(r0[j4*4])*s_a,   __uint_as_float(r0[j4*4+1])*s_a,
                __uint_as_float(r0[j4*4+2])*s_a, __uint_as_float(r0[j4*4+3])*s_a);
            *(float4*)(orow + 32 + j4*4) = make_float4(
                __uint_as_float(r1[j4*4])*s_a,   __uint_as_float(r1[j4*4+1])*s_a,
                __uint_as_float(r1[j4*4+2])*s_a, __uint_as_float(r1[j4*4+3])*s_a);
        }
    }
    TFENCE_B();
    __syncthreads();
    if (wid == 0) TDEALLOC(tmem, 64);
#endif
}

// ---------------------------------------------------------------------------
extern "C" void kernel_launch(void* const* d_in, const int* in_sizes, int n_in,
                              void* d_out, int out_size) {
    const float* x = (const float*)d_in[0];
    const int* adj = (const int*)d_in[1];
    float* out = (float*)d_out;
    float* attn = out + (size_t)BB*NN*FOUT;

    cudaFuncSetAttribute(k_pass1, cudaFuncAttributeMaxDynamicSharedMemorySize, P1_SMEM);
    cudaFuncSetAttribute(k_av,    cudaFuncAttributeMaxDynamicSharedMemorySize, AV_SMEM);

    // launch #4 = k_pass1 -> profiled by ncu
    k_init<<<1, 1>>>();
    k_merge_adj<<<dim3(512, 4), 256>>>(
        (const float*)d_in[2],  (const float*)d_in[3],  (const float*)d_in[4],  (const float*)d_in[5],
        (const float*)d_in[6],  (const float*)d_in[7],  (const float*)d_in[8],  (const float*)d_in[9],
        (const float*)d_in[10], (const float*)d_in[11], (const float*)d_in[12], (const float*)d_in[13],
        adj);
    k_proj<<<dim3(64, 12), 256>>>(x);
    k_pass1<<<dim3(8, 64), 128, P1_SMEM>>>(attn);
    k_trans_v<<<dim3(32, 2, 64), dim3(32, 8)>>>();
    k_soft<<<4096, 256>>>(attn);
    k_av<<<dim3(8, 64), 128, AV_SMEM>>>(out);
}